// round 4
// baseline (speedup 1.0000x reference)
#include <cuda_runtime.h>
#include <math.h>
#include <stdint.h>
#include <mma.h>

using namespace nvcuda;

#define NN 100000
#define NP 100096            // padded to multiple of 128
#define EE 600000
#define DD 128
#define SS 3
#define GG 64
#define OUTD 2
#define NPS (SS * NP)

// ---------------- device scratch ----------------
__device__ float g_x[NP * DD];
__device__ float g_h[NP * DD];
__device__ float g_agg[NP * DD];
__device__ float g_acc[NP * DD];
__device__ float g_gh[NP * 3 * DD];
__device__ float g_wc[SS * 2 * 3 * DD * DD];   // 6 x [384,128]
__device__ float g_pool[GG * DD];
__device__ float g_cnt[GG];
__device__ int   g_bsrc[EE];                   // CSR edge sources (by (type,dst))
__device__ int   g_ecnt[NPS];
__device__ int   g_ecur[NPS];
__device__ int   g_eoff[NPS + 1];

// ---------------- tiny utils ----------------
__global__ void zero_kernel(float* __restrict__ p, int n4) {
    int i = blockIdx.x * blockDim.x + threadIdx.x;
    if (i < n4) ((float4*)p)[i] = make_float4(0.f, 0.f, 0.f, 0.f);
}
__global__ void scale_copy_kernel(float* __restrict__ dst, const float* __restrict__ src,
                                  float s, int n4) {
    int i = blockIdx.x * blockDim.x + threadIdx.x;
    if (i < n4) {
        float4 v = ((const float4*)src)[i];
        v.x *= s; v.y *= s; v.z *= s; v.w *= s;
        ((float4*)dst)[i] = v;
    }
}
// copy x into padded xp; zero pads of xp and hp
__global__ void copy_pad_kernel(const float* __restrict__ x, float* __restrict__ xp,
                                float* __restrict__ hp) {
    int i = blockIdx.x * blockDim.x + threadIdx.x;   // over NP*32 float4 slots
    if (i >= NP * 32) return;
    int n = i >> 5;
    if (n < NN) {
        ((float4*)xp)[i] = ((const float4*)x)[i];
    } else {
        ((float4*)xp)[i] = make_float4(0.f, 0.f, 0.f, 0.f);
        ((float4*)hp)[i] = make_float4(0.f, 0.f, 0.f, 0.f);
    }
}
__global__ void zero2_ints(int* __restrict__ a, int* __restrict__ b, int n) {
    int i = blockIdx.x * blockDim.x + threadIdx.x;
    if (i < n) { a[i] = 0; b[i] = 0; }
}

// ---------------- CSR build ----------------
__global__ void ecount_kernel(const int* __restrict__ dst, const int* __restrict__ attr,
                              int* __restrict__ cnt, int E) {
    int e = blockIdx.x * blockDim.x + threadIdx.x;
    if (e < E) atomicAdd(&cnt[attr[e] * NP + dst[e]], 1);
}
// single-block exclusive scan of cnt[0..n) -> off[0..n]; off[n] = total
__global__ void scan_kernel(const int* __restrict__ cnt, int* __restrict__ off, int n) {
    __shared__ int ssum[1024];
    int t = threadIdx.x;
    int per = (n + 1023) / 1024;
    int b0 = t * per;
    int b1 = b0 + per; if (b1 > n) b1 = n; if (b0 > n) b0 = n;
    int s = 0;
    for (int i = b0; i < b1; i++) s += cnt[i];
    ssum[t] = s;
    __syncthreads();
    for (int d = 1; d < 1024; d <<= 1) {
        int v = (t >= d) ? ssum[t - d] : 0;
        __syncthreads();
        ssum[t] += v;
        __syncthreads();
    }
    int run = (t == 0) ? 0 : ssum[t - 1];
    if (t == 1023) off[n] = ssum[1023];
    for (int i = b0; i < b1; i++) { off[i] = run; run += cnt[i]; }
}
__global__ void fill_kernel(const int* __restrict__ src, const int* __restrict__ dst,
                            const int* __restrict__ attr, const int* __restrict__ off,
                            int* __restrict__ cur, int* __restrict__ bsrc, int E) {
    int e = blockIdx.x * blockDim.x + threadIdx.x;
    if (e >= E) return;
    int idx = attr[e] * NP + dst[e];
    int pos = off[idx] + atomicAdd(&cur[idx], 1);
    bsrc[pos] = src[e];
}

// ---------------- gather: agg[n] = mean over type-s in-edges of feat[src] ----
__global__ void gather_kernel(const int* __restrict__ off, const int* __restrict__ bsrc,
                              int s, const float* __restrict__ feat, float* __restrict__ agg) {
    int w = (blockIdx.x * blockDim.x + threadIdx.x) >> 5;
    int lane = threadIdx.x & 31;
    if (w >= NP) return;
    int idx = s * NP + w;
    int e0 = off[idx], e1 = off[idx + 1];
    float4 a = make_float4(0.f, 0.f, 0.f, 0.f);
    for (int e = e0; e < e1; e++) {
        int sn = bsrc[e];
        float4 v = *(const float4*)(feat + (size_t)sn * DD + lane * 4);
        a.x += v.x; a.y += v.y; a.z += v.z; a.w += v.w;
    }
    if (e1 > e0) {
        float inv = 1.0f / (float)(e1 - e0);
        a.x *= inv; a.y *= inv; a.z *= inv; a.w *= inv;
    }
    *(float4*)(agg + (size_t)w * DD + lane * 4) = a;
}

// ================= WMMA tf32 GEMM: C[M,J] = A[M,128] @ B[J,128]^T + bias =====
#define TM 128
#define TN 64
#define LDT 136
#define GEMM_SMEM ((TM + TN) * LDT * 4)

__device__ __forceinline__ float tf32r(float x) {
    float y;
    asm("cvt.rna.tf32.f32 %0, %1;" : "=f"(y) : "f"(x));
    return y;
}

__global__ void __launch_bounds__(256)
wmma_gemm_nt(const float* __restrict__ A, const float* __restrict__ B,
             float* __restrict__ C, const float* __restrict__ bias, int J,
             size_t strideA, size_t strideB, size_t strideC) {
    A += (size_t)blockIdx.z * strideA;
    B += (size_t)blockIdx.z * strideB;
    C += (size_t)blockIdx.z * strideC;
    extern __shared__ float sm[];
    float* As = sm;
    float* Bs = sm + TM * LDT;
    int tid = threadIdx.x;
    int bm = blockIdx.y * TM;
    int bn = blockIdx.x * TN;

    for (int slot = tid; slot < TM * 32; slot += 256) {
        int r = slot >> 5;
        int c4 = (slot & 31) * 4;
        float4 v = *(const float4*)(A + (size_t)(bm + r) * 128 + c4);
        v.x = tf32r(v.x); v.y = tf32r(v.y); v.z = tf32r(v.z); v.w = tf32r(v.w);
        *(float4*)(As + r * LDT + c4) = v;
    }
    for (int slot = tid; slot < TN * 32; slot += 256) {
        int r = slot >> 5;
        int c4 = (slot & 31) * 4;
        float4 v = *(const float4*)(B + (size_t)(bn + r) * 128 + c4);
        v.x = tf32r(v.x); v.y = tf32r(v.y); v.z = tf32r(v.z); v.w = tf32r(v.w);
        *(float4*)(Bs + r * LDT + c4) = v;
    }
    __syncthreads();

    int warp = tid >> 5;
    int row0 = (warp >> 1) * 32;
    int col0 = (warp & 1) * 32;

    wmma::fragment<wmma::accumulator, 16, 16, 8, float> acc[2][2];
#pragma unroll
    for (int i = 0; i < 2; i++)
#pragma unroll
        for (int j = 0; j < 2; j++) wmma::fill_fragment(acc[i][j], 0.0f);

#pragma unroll
    for (int k = 0; k < 16; k++) {
        wmma::fragment<wmma::matrix_a, 16, 16, 8, wmma::precision::tf32, wmma::row_major> a[2];
        wmma::fragment<wmma::matrix_b, 16, 16, 8, wmma::precision::tf32, wmma::col_major> b[2];
#pragma unroll
        for (int i = 0; i < 2; i++)
            wmma::load_matrix_sync(a[i], As + (row0 + i * 16) * LDT + k * 8, LDT);
#pragma unroll
        for (int j = 0; j < 2; j++)
            wmma::load_matrix_sync(b[j], Bs + (col0 + j * 16) * LDT + k * 8, LDT);
#pragma unroll
        for (int i = 0; i < 2; i++)
#pragma unroll
            for (int j = 0; j < 2; j++)
                wmma::mma_sync(acc[i][j], a[i], b[j], acc[i][j]);
    }
    __syncthreads();

    float* Cs = sm;
#pragma unroll
    for (int i = 0; i < 2; i++)
#pragma unroll
        for (int j = 0; j < 2; j++)
            wmma::store_matrix_sync(Cs + (row0 + i * 16) * TN + col0 + j * 16,
                                    acc[i][j], TN, wmma::mem_row_major);
    __syncthreads();

    for (int slot = tid; slot < TM * TN / 4; slot += 256) {
        int r = slot / (TN / 4);
        int c4 = (slot % (TN / 4)) * 4;
        float4 v = *(float4*)(Cs + r * TN + c4);
        if (bias != nullptr) {
            v.x += bias[bn + c4 + 0];
            v.y += bias[bn + c4 + 1];
            v.z += bias[bn + c4 + 2];
            v.w += bias[bn + c4 + 3];
        }
        *(float4*)(C + (size_t)(bm + r) * J + bn + c4) = v;
    }
}

// ========== fused gi GEMM + GRU: per CTA 128 rows x 64 gate-dims (192 B-rows) ==========
#define FTM 128
#define FTN 192
#define FUSED_SMEM ((FTM + FTN) * LDT * 4)   // 174080

__device__ __forceinline__ float sigf(float x) { return 1.0f / (1.0f + expf(-x)); }

__global__ void __launch_bounds__(256)
fused_gi_gru(const float* __restrict__ agg, const float* __restrict__ Wc,
             const float* __restrict__ bih_s, const float* __restrict__ gh,
             const float* __restrict__ hold, float* __restrict__ hout,
             float* __restrict__ accb, int mode) {
    extern __shared__ float sm[];
    float* As = sm;                  // [FTM][LDT]
    float* Bs = sm + FTM * LDT;      // [FTN][LDT]
    int tid = threadIdx.x;
    int c0 = blockIdx.x * 64;        // gate-dim block
    int bm = blockIdx.y * FTM;

    // A tile: agg rows (pre-scaled by gather)
    for (int slot = tid; slot < FTM * 32; slot += 256) {
        int r = slot >> 5;
        int c4 = (slot & 31) * 4;
        float4 v = *(const float4*)(agg + (size_t)(bm + r) * 128 + c4);
        v.x = tf32r(v.x); v.y = tf32r(v.y); v.z = tf32r(v.z); v.w = tf32r(v.w);
        *(float4*)(As + r * LDT + c4) = v;
    }
    // B tile: Wc rows {g*128 + c0 + jj} for g in 0..2, jj in 0..63
    for (int slot = tid; slot < FTN * 32; slot += 256) {
        int jp = slot >> 5;
        int c4 = (slot & 31) * 4;
        int grow = (jp >> 6) * 128 + c0 + (jp & 63);
        float4 v = *(const float4*)(Wc + (size_t)grow * 128 + c4);
        v.x = tf32r(v.x); v.y = tf32r(v.y); v.z = tf32r(v.z); v.w = tf32r(v.w);
        *(float4*)(Bs + jp * LDT + c4) = v;
    }
    __syncthreads();

    int warp = tid >> 5;
    int row0 = (warp >> 1) * 32;     // 4 row bands of 32
    int col0 = (warp & 1) * 96;      // 2 col bands of 96

    wmma::fragment<wmma::accumulator, 16, 16, 8, float> acc[2][6];
#pragma unroll
    for (int i = 0; i < 2; i++)
#pragma unroll
        for (int j = 0; j < 6; j++) wmma::fill_fragment(acc[i][j], 0.0f);

#pragma unroll
    for (int k = 0; k < 16; k++) {
        wmma::fragment<wmma::matrix_a, 16, 16, 8, wmma::precision::tf32, wmma::row_major> a[2];
        wmma::fragment<wmma::matrix_b, 16, 16, 8, wmma::precision::tf32, wmma::col_major> b[6];
#pragma unroll
        for (int i = 0; i < 2; i++)
            wmma::load_matrix_sync(a[i], As + (row0 + i * 16) * LDT + k * 8, LDT);
#pragma unroll
        for (int j = 0; j < 6; j++)
            wmma::load_matrix_sync(b[j], Bs + (col0 + j * 16) * LDT + k * 8, LDT);
#pragma unroll
        for (int i = 0; i < 2; i++)
#pragma unroll
            for (int j = 0; j < 6; j++)
                wmma::mma_sync(acc[i][j], a[i], b[j], acc[i][j]);
    }
    __syncthreads();

    float* Cs = sm;                  // [FTM][FTN] = 98304 B, fits in smem
#pragma unroll
    for (int i = 0; i < 2; i++)
#pragma unroll
        for (int j = 0; j < 6; j++)
            wmma::store_matrix_sync(Cs + (row0 + i * 16) * FTN + col0 + j * 16,
                                    acc[i][j], FTN, wmma::mem_row_major);
    __syncthreads();

    // epilogue: GRU on 128 rows x 64 dims
    for (int slot = tid; slot < FTM * 16; slot += 256) {
        int r = slot >> 4;
        int cc = (slot & 15) * 4;
        int grow = bm + r;
        const float* crow = Cs + r * FTN;
        float4 ir = *(const float4*)(crow + cc);
        float4 iz = *(const float4*)(crow + 64 + cc);
        float4 in4 = *(const float4*)(crow + 128 + cc);
        float4 br = *(const float4*)(bih_s + c0 + cc);
        float4 bz = *(const float4*)(bih_s + 128 + c0 + cc);
        float4 bn4 = *(const float4*)(bih_s + 256 + c0 + cc);
        ir.x += br.x; ir.y += br.y; ir.z += br.z; ir.w += br.w;
        iz.x += bz.x; iz.y += bz.y; iz.z += bz.z; iz.w += bz.w;
        in4.x += bn4.x; in4.y += bn4.y; in4.z += bn4.z; in4.w += bn4.w;
        const float* ghr = gh + (size_t)grow * 384;
        float4 hr = *(const float4*)(ghr + c0 + cc);
        float4 hz = *(const float4*)(ghr + 128 + c0 + cc);
        float4 hn = *(const float4*)(ghr + 256 + c0 + cc);
        float4 h = *(const float4*)(hold + (size_t)grow * 128 + c0 + cc);
        float4 o;
        { float rr = sigf(ir.x + hr.x), z = sigf(iz.x + hz.x);
          float nn = tanhf(in4.x + rr * hn.x); o.x = (1.f - z) * nn + z * h.x; }
        { float rr = sigf(ir.y + hr.y), z = sigf(iz.y + hz.y);
          float nn = tanhf(in4.y + rr * hn.y); o.y = (1.f - z) * nn + z * h.y; }
        { float rr = sigf(ir.z + hr.z), z = sigf(iz.z + hz.z);
          float nn = tanhf(in4.z + rr * hn.z); o.z = (1.f - z) * nn + z * h.z; }
        { float rr = sigf(ir.w + hr.w), z = sigf(iz.w + hz.w);
          float nn = tanhf(in4.w + rr * hn.w); o.w = (1.f - z) * nn + z * h.w; }
        *(float4*)(hout + (size_t)grow * 128 + c0 + cc) = o;
        if (mode == 1) {
            *(float4*)(accb + (size_t)grow * 128 + c0 + cc) = o;
        } else if (mode == 2) {
            float* ap = accb + (size_t)grow * 128 + c0 + cc;
            float4 av = *(float4*)ap;
            av.x += o.x; av.y += o.y; av.z += o.z; av.w += o.w;
            *(float4*)ap = av;
        }
    }
}

// ---------------- pooling / MLP ----------------
__global__ void cnt_kernel(const int* __restrict__ batch, float* __restrict__ cnt, int n) {
    int i = blockIdx.x * blockDim.x + threadIdx.x;
    if (i < n) atomicAdd(&cnt[batch[i]], 1.0f);
}
__global__ void pool_kernel(const float* __restrict__ x, const int* __restrict__ batch,
                            float* __restrict__ pool) {
    int idx = blockIdx.x * blockDim.x + threadIdx.x;
    if (idx >= NN * 32) return;
    int n = idx >> 5;
    int c = (idx & 31) * 4;
    int g = batch[n];
    float4 v = *(const float4*)(x + (size_t)n * 128 + c);
    float* o = pool + (size_t)g * 128 + c;
    asm volatile("red.global.add.v4.f32 [%0], {%1,%2,%3,%4};"
                 :: "l"(o), "f"(v.x), "f"(v.y), "f"(v.z), "f"(v.w) : "memory");
}
__global__ void mlp_kernel(const float* __restrict__ pool, const float* __restrict__ cnt,
                           const float* __restrict__ pt,
                           const float* __restrict__ fc1w, const float* __restrict__ fc1b,
                           const float* __restrict__ fc2w, const float* __restrict__ fc2b,
                           const float* __restrict__ fclw, const float* __restrict__ fclb,
                           float* __restrict__ out) {
    __shared__ float h1[GG * 80];
    __shared__ float h2[GG * 80];
    int tid = threadIdx.x;
    for (int t = tid; t < GG * 80; t += blockDim.x) {
        int g = t / 80, j = t - (t / 80) * 80;
        float ic = 1.0f / fmaxf(cnt[g], 1.0f);
        float acc = fc1b[j];
        const float* w = fc1w + j * 129;
        const float* p = pool + g * 128;
        for (int k = 0; k < 128; k++) acc = fmaf(p[k] * ic, w[k], acc);
        acc = fmaf(pt[g], w[128], acc);
        h1[t] = acc > 0.f ? acc : 0.01f * acc;
    }
    __syncthreads();
    for (int t = tid; t < GG * 80; t += blockDim.x) {
        int g = t / 80, j = t - (t / 80) * 80;
        float acc = fc2b[j];
        const float* w = fc2w + j * 80;
        const float* hh = h1 + g * 80;
        for (int k = 0; k < 80; k++) acc = fmaf(hh[k], w[k], acc);
        h2[t] = acc > 0.f ? acc : 0.01f * acc;
    }
    __syncthreads();
    for (int t = tid; t < GG * OUTD; t += blockDim.x) {
        int g = t / OUTD, o = t - (t / OUTD) * OUTD;
        float acc = fclb[o];
        const float* w = fclw + o * 80;
        const float* hh = h2 + g * 80;
        for (int k = 0; k < 80; k++) acc = fmaf(hh[k], w[k], acc);
        out[t] = acc;
    }
}

// ---------------- host launcher ----------------
extern "C" void kernel_launch(void* const* d_in, const int* in_sizes, int n_in,
                              void* d_out, int out_size) {
    (void)in_sizes; (void)n_in; (void)out_size;
    const float* x     = (const float*)d_in[0];
    const int*   eidx  = (const int*)d_in[1];
    const int*   eattr = (const int*)d_in[2];
    const int*   batch = (const int*)d_in[3];
    const float* pt    = (const float*)d_in[4];
    const float* W     = (const float*)d_in[5];
    const float* wih   = (const float*)d_in[6];
    const float* whh   = (const float*)d_in[7];
    const float* bih   = (const float*)d_in[8];
    const float* bhh   = (const float*)d_in[9];
    const float* fc1w  = (const float*)d_in[10];
    const float* fc1b  = (const float*)d_in[11];
    const float* fc2w  = (const float*)d_in[12];
    const float* fc2b  = (const float*)d_in[13];
    const float* fclw  = (const float*)d_in[14];
    const float* fclb  = (const float*)d_in[15];
    float* out = (float*)d_out;

    const int* src = eidx;
    const int* dst = eidx + EE;

    float *xp, *hp, *aggp, *accp, *ghp, *wcp, *poolp, *cntp;
    int *bsrcp, *ecntp, *ecurp, *eoffp;
    cudaGetSymbolAddress((void**)&xp,    g_x);
    cudaGetSymbolAddress((void**)&hp,    g_h);
    cudaGetSymbolAddress((void**)&aggp,  g_agg);
    cudaGetSymbolAddress((void**)&accp,  g_acc);
    cudaGetSymbolAddress((void**)&ghp,   g_gh);
    cudaGetSymbolAddress((void**)&wcp,   g_wc);
    cudaGetSymbolAddress((void**)&poolp, g_pool);
    cudaGetSymbolAddress((void**)&cntp,  g_cnt);
    cudaGetSymbolAddress((void**)&bsrcp, g_bsrc);
    cudaGetSymbolAddress((void**)&ecntp, g_ecnt);
    cudaGetSymbolAddress((void**)&ecurp, g_ecur);
    cudaGetSymbolAddress((void**)&eoffp, g_eoff);

    cudaFuncSetAttribute(wmma_gemm_nt, cudaFuncAttributeMaxDynamicSharedMemorySize, GEMM_SMEM);
    cudaFuncSetAttribute(fused_gi_gru, cudaFuncAttributeMaxDynamicSharedMemorySize, FUSED_SMEM);

    const int TB = 256;
    dim3 gh_grid(6, NP / TM);            // (6, 782)
    dim3 wc_grid(2, 3, 6);               // batched 6x [384,128]
    dim3 fu_grid(2, NP / FTM);           // (2, 782)

    // launch 0: copy + pad
    copy_pad_kernel<<<(NP * 32 + TB - 1) / TB, TB>>>(x, xp, hp);
    // launch 1: combined weights Wc[s,i] = wih[s] @ W[s,i]  (batched)
    wmma_gemm_nt<<<wc_grid, TB, GEMM_SMEM>>>(wih, W, wcp, nullptr, 128,
                                             (size_t)0, (size_t)(128 * 128), (size_t)(384 * 128));
    // note: strideA handled below — wih repeats per (s,i): use z/2 trick not available, so
    // we instead launch per-s to keep A stride correct (2 extra launches before index 3 avoided
    // by folding: A stride must map z->s. Simplest correct: relaunch with strideA=0 per s pair.)
    // The single launch above is WRONG for s>0; fix with two more small launches AFTER index 3.

    // launch 2: zero CSR count/cursor arrays
    zero2_ints<<<(NPS + TB - 1) / TB, TB>>>(ecntp, ecurp, NPS);
    // launch 3 (PROFILED): gh GEMM for pass0,s0,i0 — full size
    wmma_gemm_nt<<<gh_grid, TB, GEMM_SMEM>>>(xp, whh, ghp, bhh, 384,
                                             (size_t)0, (size_t)0, (size_t)0);
    // fix-up wc for s=1,2 (launch 1 computed z in 0..5 with A=wih[0] for all; recompute z>=2)
    wmma_gemm_nt<<<dim3(2, 3, 2), TB, GEMM_SMEM>>>(
        wih + (size_t)1 * 384 * 128, W + (size_t)2 * 128 * 128, wcp + (size_t)2 * 384 * 128,
        nullptr, 128, (size_t)0, (size_t)(128 * 128), (size_t)(384 * 128));
    wmma_gemm_nt<<<dim3(2, 3, 2), TB, GEMM_SMEM>>>(
        wih + (size_t)2 * 384 * 128, W + (size_t)4 * 128 * 128, wcp + (size_t)4 * 384 * 128,
        nullptr, 128, (size_t)0, (size_t)(128 * 128), (size_t)(384 * 128));
    // CSR build
    ecount_kernel<<<(EE + TB - 1) / TB, TB>>>(dst, eattr, ecntp, EE);
    scan_kernel<<<1, 1024>>>(ecntp, eoffp, NPS);
    fill_kernel<<<(EE + TB - 1) / TB, TB>>>(src, dst, eattr, eoffp, ecurp, bsrcp, EE);

    // --- main GGNN loop ---
    bool first = true;
    for (int pass = 0; pass < 2; pass++) {
        for (int s = 0; s < SS; s++) {
            for (int i = 0; i < 2; i++) {
                const float* hin = (i == 0) ? xp : hp;
                if (!first) {
                    wmma_gemm_nt<<<gh_grid, TB, GEMM_SMEM>>>(
                        hin, whh + (size_t)s * 384 * 128, ghp, bhh + s * 384, 384,
                        (size_t)0, (size_t)0, (size_t)0);
                }
                first = false;
                gather_kernel<<<(NP * 32 + TB - 1) / TB, TB>>>(eoffp, bsrcp, s, hin, aggp);
                int mode = (i == 1) ? ((s == 0) ? 1 : 2) : 0;
                fused_gi_gru<<<fu_grid, TB, FUSED_SMEM>>>(
                    aggp, wcp + (size_t)(s * 2 + i) * 384 * 128, bih + s * 384,
                    ghp, hin, hp, accp, mode);
            }
        }
        scale_copy_kernel<<<(NN * DD / 4 + TB - 1) / TB, TB>>>(xp, accp, 1.0f / 3.0f,
                                                               NN * DD / 4);
    }

    // --- pooling + MLP ---
    zero_kernel<<<(GG * DD / 4 + TB - 1) / TB, TB>>>(poolp, GG * DD / 4);
    zero_kernel<<<1, GG / 4>>>(cntp, GG / 4);
    cnt_kernel<<<(NN + TB - 1) / TB, TB>>>(batch, cntp, NN);
    pool_kernel<<<(NN * 32 + TB - 1) / TB, TB>>>(xp, batch, poolp);
    mlp_kernel<<<1, 256>>>(poolp, cntp, pt, fc1w, fc1b, fc2w, fc2b, fclw, fclb, out);
}

// round 5
// speedup vs baseline: 2.0784x; 2.0784x over previous
#include <cuda_runtime.h>
#include <cuda_bf16.h>
#include <math.h>
#include <stdint.h>
#include <mma.h>

using namespace nvcuda;

#define NN 100000
#define NP 100096
#define EE 600000
#define DD 128
#define SS 3
#define GG 64
#define OUTD 2
#define NPS (SS * NP)

// ---------------- device scratch ----------------
__device__ float g_x[NP * DD];
__device__ float g_h[NP * DD];
__device__ float g_agg[NP * DD];
__device__ float g_acc[NP * DD];
__device__ __nv_bfloat16 g_gh[NP * 3 * DD];
__device__ __nv_bfloat16 g_gi[NP * 3 * DD];
__device__ float g_wc[SS * 2 * 3 * DD * DD];   // 6 x [384,128] fp32
__device__ float g_pool[GG * DD];
__device__ float g_cnt[GG];
__device__ int   g_bsrc[EE];
__device__ int   g_ecnt[NPS];
__device__ int   g_ecur[NPS];
__device__ int   g_eoff[NPS + 1];

// ---------------- tiny utils ----------------
__global__ void zero_kernel(float* __restrict__ p, int n4) {
    int i = blockIdx.x * blockDim.x + threadIdx.x;
    if (i < n4) ((float4*)p)[i] = make_float4(0.f, 0.f, 0.f, 0.f);
}
__global__ void scale_copy_kernel(float* __restrict__ dst, const float* __restrict__ src,
                                  float s, int n4) {
    int i = blockIdx.x * blockDim.x + threadIdx.x;
    if (i < n4) {
        float4 v = ((const float4*)src)[i];
        v.x *= s; v.y *= s; v.z *= s; v.w *= s;
        ((float4*)dst)[i] = v;
    }
}
__global__ void copy_pad_kernel(const float* __restrict__ x, float* __restrict__ xp,
                                float* __restrict__ hp) {
    int i = blockIdx.x * blockDim.x + threadIdx.x;
    if (i >= NP * 32) return;
    int n = i >> 5;
    if (n < NN) {
        ((float4*)xp)[i] = ((const float4*)x)[i];
    } else {
        ((float4*)xp)[i] = make_float4(0.f, 0.f, 0.f, 0.f);
        ((float4*)hp)[i] = make_float4(0.f, 0.f, 0.f, 0.f);
    }
}
__global__ void zero2_ints(int* __restrict__ a, int* __restrict__ b, int n) {
    int i = blockIdx.x * blockDim.x + threadIdx.x;
    if (i < n) { a[i] = 0; b[i] = 0; }
}

// ---------------- CSR build ----------------
__global__ void ecount_kernel(const int* __restrict__ dst, const int* __restrict__ attr,
                              int* __restrict__ cnt, int E) {
    int e = blockIdx.x * blockDim.x + threadIdx.x;
    if (e < E) atomicAdd(&cnt[attr[e] * NP + dst[e]], 1);
}
__global__ void scan_kernel(const int* __restrict__ cnt, int* __restrict__ off, int n) {
    __shared__ int ssum[1024];
    int t = threadIdx.x;
    int per = (n + 1023) / 1024;
    int b0 = t * per;
    int b1 = b0 + per; if (b1 > n) b1 = n; if (b0 > n) b0 = n;
    int s = 0;
    for (int i = b0; i < b1; i++) s += cnt[i];
    ssum[t] = s;
    __syncthreads();
    for (int d = 1; d < 1024; d <<= 1) {
        int v = (t >= d) ? ssum[t - d] : 0;
        __syncthreads();
        ssum[t] += v;
        __syncthreads();
    }
    int run = (t == 0) ? 0 : ssum[t - 1];
    if (t == 1023) off[n] = ssum[1023];
    for (int i = b0; i < b1; i++) { off[i] = run; run += cnt[i]; }
}
__global__ void fill_kernel(const int* __restrict__ src, const int* __restrict__ dst,
                            const int* __restrict__ attr, const int* __restrict__ off,
                            int* __restrict__ cur, int* __restrict__ bsrc, int E) {
    int e = blockIdx.x * blockDim.x + threadIdx.x;
    if (e >= E) return;
    int idx = attr[e] * NP + dst[e];
    int pos = off[idx] + atomicAdd(&cur[idx], 1);
    bsrc[pos] = src[e];
}

// ---------------- gather: agg[n] = mean over type-s in-edges of feat[src] ----
__global__ void gather_kernel(const int* __restrict__ off, const int* __restrict__ bsrc,
                              int s, const float* __restrict__ feat, float* __restrict__ agg) {
    int w = (blockIdx.x * blockDim.x + threadIdx.x) >> 5;
    int lane = threadIdx.x & 31;
    if (w >= NP) return;
    int idx = s * NP + w;
    int e0 = off[idx], e1 = off[idx + 1];
    float4 a = make_float4(0.f, 0.f, 0.f, 0.f);
    for (int e = e0; e < e1; e++) {
        int sn = bsrc[e];
        float4 v = *(const float4*)(feat + (size_t)sn * DD + lane * 4);
        a.x += v.x; a.y += v.y; a.z += v.z; a.w += v.w;
    }
    if (e1 > e0) {
        float inv = 1.0f / (float)(e1 - e0);
        a.x *= inv; a.y *= inv; a.z *= inv; a.w *= inv;
    }
    *(float4*)(agg + (size_t)w * DD + lane * 4) = a;
}

// ================= bf16 WMMA GEMM: C = A[M,128] @ B[J,128]^T + bias ==========
// CTA tile 128x128, K=128 resident, warp tile 32x64, m16n16k16.
// Dual mode (A1 != null): blockIdx.z selects parameter set {A0,...} / {A1,...}.
// Non-dual: strided batch over z. out_bf16 selects output dtype.
#define LDTB 136
#define LDC 132
#define BG_SMEM (256 * LDTB * 2)   // 69632 bytes

__global__ void __launch_bounds__(256, 2)
bf16_gemm(const float* __restrict__ A0, const float* __restrict__ B0,
          const float* __restrict__ bias0, void* __restrict__ C0v,
          const float* __restrict__ A1, const float* __restrict__ B1,
          const float* __restrict__ bias1, void* __restrict__ C1v,
          int J, int out_bf16, size_t sA, size_t sB, size_t sC) {
    const float *A, *B, *bias;
    void* C;
    if (A1 != nullptr) {
        if (blockIdx.z == 0) { A = A0; B = B0; bias = bias0; C = C0v; }
        else                 { A = A1; B = B1; bias = bias1; C = C1v; }
    } else {
        A = A0 + (size_t)blockIdx.z * sA;
        B = B0 + (size_t)blockIdx.z * sB;
        bias = bias0;
        C = (void*)((float*)C0v + (size_t)blockIdx.z * sC);
    }

    extern __shared__ char smx[];
    __nv_bfloat16* As = (__nv_bfloat16*)smx;
    __nv_bfloat16* Bs = As + 128 * LDTB;
    float* Cs = (float*)smx;

    int tid = threadIdx.x;
    int bm = blockIdx.y * 128;
    int bn = blockIdx.x * 128;

    // load + convert A and B tiles (each 128 rows x 128 cols)
    for (int slot = tid; slot < 128 * 32; slot += 256) {
        int r = slot >> 5;
        int c4 = (slot & 31) * 4;
        float4 v = *(const float4*)(A + (size_t)(bm + r) * 128 + c4);
        *(__nv_bfloat162*)(As + r * LDTB + c4)     = __floats2bfloat162_rn(v.x, v.y);
        *(__nv_bfloat162*)(As + r * LDTB + c4 + 2) = __floats2bfloat162_rn(v.z, v.w);
        float4 w = *(const float4*)(B + (size_t)(bn + r) * 128 + c4);
        *(__nv_bfloat162*)(Bs + r * LDTB + c4)     = __floats2bfloat162_rn(w.x, w.y);
        *(__nv_bfloat162*)(Bs + r * LDTB + c4 + 2) = __floats2bfloat162_rn(w.z, w.w);
    }
    __syncthreads();

    int warp = tid >> 5;
    int row0 = (warp >> 1) * 32;   // 4 row bands
    int col0 = (warp & 1) * 64;    // 2 col bands

    wmma::fragment<wmma::accumulator, 16, 16, 16, float> acc[2][4];
#pragma unroll
    for (int i = 0; i < 2; i++)
#pragma unroll
        for (int j = 0; j < 4; j++) wmma::fill_fragment(acc[i][j], 0.0f);

#pragma unroll
    for (int k = 0; k < 8; k++) {
        wmma::fragment<wmma::matrix_a, 16, 16, 16, __nv_bfloat16, wmma::row_major> a[2];
        wmma::fragment<wmma::matrix_b, 16, 16, 16, __nv_bfloat16, wmma::col_major> b[4];
#pragma unroll
        for (int i = 0; i < 2; i++)
            wmma::load_matrix_sync(a[i], As + (row0 + i * 16) * LDTB + k * 16, LDTB);
#pragma unroll
        for (int j = 0; j < 4; j++)
            wmma::load_matrix_sync(b[j], Bs + (col0 + j * 16) * LDTB + k * 16, LDTB);
#pragma unroll
        for (int i = 0; i < 2; i++)
#pragma unroll
            for (int j = 0; j < 4; j++)
                wmma::mma_sync(acc[i][j], a[i], b[j], acc[i][j]);
    }
    __syncthreads();

#pragma unroll
    for (int i = 0; i < 2; i++)
#pragma unroll
        for (int j = 0; j < 4; j++)
            wmma::store_matrix_sync(Cs + (row0 + i * 16) * LDC + col0 + j * 16,
                                    acc[i][j], LDC, wmma::mem_row_major);
    __syncthreads();

    for (int slot = tid; slot < 128 * 32; slot += 256) {
        int r = slot >> 5;
        int c4 = (slot & 31) * 4;
        float4 v = *(float4*)(Cs + r * LDC + c4);
        if (bias != nullptr) {
            v.x += bias[bn + c4 + 0];
            v.y += bias[bn + c4 + 1];
            v.z += bias[bn + c4 + 2];
            v.w += bias[bn + c4 + 3];
        }
        if (out_bf16) {
            __nv_bfloat16* crow = (__nv_bfloat16*)C + (size_t)(bm + r) * J + bn + c4;
            *(__nv_bfloat162*)(crow)     = __floats2bfloat162_rn(v.x, v.y);
            *(__nv_bfloat162*)(crow + 2) = __floats2bfloat162_rn(v.z, v.w);
        } else {
            *(float4*)((float*)C + (size_t)(bm + r) * J + bn + c4) = v;
        }
    }
}

// ---------------- GRU elementwise combine (bf16 gates) ----------------
__device__ __forceinline__ float sigf(float x) { return 1.0f / (1.0f + expf(-x)); }

__device__ __forceinline__ float4 ldbf4(const __nv_bfloat16* p) {
    uint2 u = *(const uint2*)p;
    __nv_bfloat162 a = *(__nv_bfloat162*)&u.x;
    __nv_bfloat162 b = *(__nv_bfloat162*)&u.y;
    float2 fa = __bfloat1622float2(a), fb = __bfloat1622float2(b);
    return make_float4(fa.x, fa.y, fb.x, fb.y);
}

__global__ void gru_combine_kernel(const __nv_bfloat16* __restrict__ gi,
                                   const __nv_bfloat16* __restrict__ gh,
                                   const float* __restrict__ hold, float* __restrict__ hout,
                                   float* __restrict__ accb, int mode) {
    int idx = blockIdx.x * blockDim.x + threadIdx.x;
    if (idx >= NN * 32) return;
    int n = idx >> 5;
    int c = (idx & 31) * 4;
    const __nv_bfloat16* gir = gi + (size_t)n * 384;
    const __nv_bfloat16* ghr = gh + (size_t)n * 384;
    float4 ir = ldbf4(gir + c);
    float4 iz = ldbf4(gir + 128 + c);
    float4 in4 = ldbf4(gir + 256 + c);
    float4 hr = ldbf4(ghr + c);
    float4 hz = ldbf4(ghr + 128 + c);
    float4 hn = ldbf4(ghr + 256 + c);
    float4 h = *(const float4*)(hold + (size_t)n * 128 + c);
    float4 o;
    { float r = sigf(ir.x + hr.x), z = sigf(iz.x + hz.x);
      float nn = tanhf(in4.x + r * hn.x); o.x = (1.f - z) * nn + z * h.x; }
    { float r = sigf(ir.y + hr.y), z = sigf(iz.y + hz.y);
      float nn = tanhf(in4.y + r * hn.y); o.y = (1.f - z) * nn + z * h.y; }
    { float r = sigf(ir.z + hr.z), z = sigf(iz.z + hz.z);
      float nn = tanhf(in4.z + r * hn.z); o.z = (1.f - z) * nn + z * h.z; }
    { float r = sigf(ir.w + hr.w), z = sigf(iz.w + hz.w);
      float nn = tanhf(in4.w + r * hn.w); o.w = (1.f - z) * nn + z * h.w; }
    *(float4*)(hout + (size_t)n * 128 + c) = o;
    if (mode == 1) {
        *(float4*)(accb + (size_t)n * 128 + c) = o;
    } else if (mode == 2) {
        float* ap = accb + (size_t)n * 128 + c;
        float4 av = *(float4*)ap;
        av.x += o.x; av.y += o.y; av.z += o.z; av.w += o.w;
        *(float4*)ap = av;
    }
}

// ---------------- pooling / MLP ----------------
__global__ void cnt_kernel(const int* __restrict__ batch, float* __restrict__ cnt, int n) {
    int i = blockIdx.x * blockDim.x + threadIdx.x;
    if (i < n) atomicAdd(&cnt[batch[i]], 1.0f);
}
__global__ void pool_kernel(const float* __restrict__ x, const int* __restrict__ batch,
                            float* __restrict__ pool) {
    int idx = blockIdx.x * blockDim.x + threadIdx.x;
    if (idx >= NN * 32) return;
    int n = idx >> 5;
    int c = (idx & 31) * 4;
    int g = batch[n];
    float4 v = *(const float4*)(x + (size_t)n * 128 + c);
    float* o = pool + (size_t)g * 128 + c;
    asm volatile("red.global.add.v4.f32 [%0], {%1,%2,%3,%4};"
                 :: "l"(o), "f"(v.x), "f"(v.y), "f"(v.z), "f"(v.w) : "memory");
}
__global__ void mlp_kernel(const float* __restrict__ pool, const float* __restrict__ cnt,
                           const float* __restrict__ pt,
                           const float* __restrict__ fc1w, const float* __restrict__ fc1b,
                           const float* __restrict__ fc2w, const float* __restrict__ fc2b,
                           const float* __restrict__ fclw, const float* __restrict__ fclb,
                           float* __restrict__ out) {
    __shared__ float h1[GG * 80];
    __shared__ float h2[GG * 80];
    int tid = threadIdx.x;
    for (int t = tid; t < GG * 80; t += blockDim.x) {
        int g = t / 80, j = t - (t / 80) * 80;
        float ic = 1.0f / fmaxf(cnt[g], 1.0f);
        float acc = fc1b[j];
        const float* w = fc1w + j * 129;
        const float* p = pool + g * 128;
        for (int k = 0; k < 128; k++) acc = fmaf(p[k] * ic, w[k], acc);
        acc = fmaf(pt[g], w[128], acc);
        h1[t] = acc > 0.f ? acc : 0.01f * acc;
    }
    __syncthreads();
    for (int t = tid; t < GG * 80; t += blockDim.x) {
        int g = t / 80, j = t - (t / 80) * 80;
        float acc = fc2b[j];
        const float* w = fc2w + j * 80;
        const float* hh = h1 + g * 80;
        for (int k = 0; k < 80; k++) acc = fmaf(hh[k], w[k], acc);
        h2[t] = acc > 0.f ? acc : 0.01f * acc;
    }
    __syncthreads();
    for (int t = tid; t < GG * OUTD; t += blockDim.x) {
        int g = t / OUTD, o = t - (t / OUTD) * OUTD;
        float acc = fclb[o];
        const float* w = fclw + o * 80;
        const float* hh = h2 + g * 80;
        for (int k = 0; k < 80; k++) acc = fmaf(hh[k], w[k], acc);
        out[t] = acc;
    }
}

// ---------------- host launcher ----------------
extern "C" void kernel_launch(void* const* d_in, const int* in_sizes, int n_in,
                              void* d_out, int out_size) {
    (void)in_sizes; (void)n_in; (void)out_size;
    const float* x     = (const float*)d_in[0];
    const int*   eidx  = (const int*)d_in[1];
    const int*   eattr = (const int*)d_in[2];
    const int*   batch = (const int*)d_in[3];
    const float* pt    = (const float*)d_in[4];
    const float* W     = (const float*)d_in[5];
    const float* wih   = (const float*)d_in[6];
    const float* whh   = (const float*)d_in[7];
    const float* bih   = (const float*)d_in[8];
    const float* bhh   = (const float*)d_in[9];
    const float* fc1w  = (const float*)d_in[10];
    const float* fc1b  = (const float*)d_in[11];
    const float* fc2w  = (const float*)d_in[12];
    const float* fc2b  = (const float*)d_in[13];
    const float* fclw  = (const float*)d_in[14];
    const float* fclb  = (const float*)d_in[15];
    float* out = (float*)d_out;

    const int* src = eidx;
    const int* dst = eidx + EE;

    float *xp, *hp, *aggp, *accp, *wcp, *poolp, *cntp;
    __nv_bfloat16 *ghp, *gip;
    int *bsrcp, *ecntp, *ecurp, *eoffp;
    cudaGetSymbolAddress((void**)&xp,    g_x);
    cudaGetSymbolAddress((void**)&hp,    g_h);
    cudaGetSymbolAddress((void**)&aggp,  g_agg);
    cudaGetSymbolAddress((void**)&accp,  g_acc);
    cudaGetSymbolAddress((void**)&ghp,   g_gh);
    cudaGetSymbolAddress((void**)&gip,   g_gi);
    cudaGetSymbolAddress((void**)&wcp,   g_wc);
    cudaGetSymbolAddress((void**)&poolp, g_pool);
    cudaGetSymbolAddress((void**)&cntp,  g_cnt);
    cudaGetSymbolAddress((void**)&bsrcp, g_bsrc);
    cudaGetSymbolAddress((void**)&ecntp, g_ecnt);
    cudaGetSymbolAddress((void**)&ecurp, g_ecur);
    cudaGetSymbolAddress((void**)&eoffp, g_eoff);

    cudaFuncSetAttribute(bf16_gemm, cudaFuncAttributeMaxDynamicSharedMemorySize, BG_SMEM);

    const int TB = 256;
    dim3 main_grid1(3, NP / 128, 1);     // single-source GEMM (M=NP, J=384)
    dim3 main_grid2(3, NP / 128, 2);     // dual gh+gi GEMM
    dim3 wc_grid(1, 3, 2);               // per-s batched: M=384, J=128, z=i

    // 0: copy + pad
    copy_pad_kernel<<<(NP * 32 + TB - 1) / TB, TB>>>(x, xp, hp);
    // 1: zero CSR arrays
    zero2_ints<<<(NPS + TB - 1) / TB, TB>>>(ecntp, ecurp, NPS);
    // 2: per-(type,dst) counts
    ecount_kernel<<<(EE + TB - 1) / TB, TB>>>(dst, eattr, ecntp, EE);
    // 3 (PROFILED): gh GEMM for step (0,0,0)
    bf16_gemm<<<main_grid1, TB, BG_SMEM>>>(xp, whh, bhh, ghp,
                                           nullptr, nullptr, nullptr, nullptr,
                                           384, 1, 0, 0, 0);
    // CSR scan + fill
    scan_kernel<<<1, 1024>>>(ecntp, eoffp, NPS);
    fill_kernel<<<(EE + TB - 1) / TB, TB>>>(src, dst, eattr, eoffp, ecurp, bsrcp, EE);
    // combined weights Wc[s,i][j,c] = sum_{c'} wih[s][j,c'] * W[s,i][c,c']  (fp32 out)
    for (int s = 0; s < SS; s++)
        bf16_gemm<<<wc_grid, TB, BG_SMEM>>>(
            wih + (size_t)s * 384 * 128, W + (size_t)(s * 2) * 128 * 128, nullptr,
            wcp + (size_t)(s * 2) * 384 * 128,
            nullptr, nullptr, nullptr, nullptr,
            128, 0, (size_t)0, (size_t)(128 * 128), (size_t)(384 * 128));

    // --- main GGNN loop ---
    for (int pass = 0; pass < 2; pass++) {
        for (int s = 0; s < SS; s++) {
            for (int i = 0; i < 2; i++) {
                const float* hin = (i == 0) ? xp : hp;
                const float* wc_si = wcp + (size_t)(s * 2 + i) * 384 * 128;
                gather_kernel<<<(NP * 32 + TB - 1) / TB, TB>>>(eoffp, bsrcp, s, hin, aggp);
                if (pass == 0 && s == 0 && i == 0) {
                    // gh already computed at launch 3; gi only
                    bf16_gemm<<<main_grid1, TB, BG_SMEM>>>(aggp, wc_si, bih, gip,
                                                           nullptr, nullptr, nullptr, nullptr,
                                                           384, 1, 0, 0, 0);
                } else {
                    bf16_gemm<<<main_grid2, TB, BG_SMEM>>>(
                        hin, whh + (size_t)s * 384 * 128, bhh + s * 384, ghp,
                        aggp, wc_si, bih + s * 384, gip,
                        384, 1, 0, 0, 0);
                }
                int mode = (i == 1) ? ((s == 0) ? 1 : 2) : 0;
                gru_combine_kernel<<<(NN * 32 + TB - 1) / TB, TB>>>(gip, ghp, hin, hp,
                                                                    accp, mode);
            }
        }
        scale_copy_kernel<<<(NN * DD / 4 + TB - 1) / TB, TB>>>(xp, accp, 1.0f / 3.0f,
                                                               NN * DD / 4);
    }

    // --- pooling + MLP ---
    zero_kernel<<<(GG * DD / 4 + TB - 1) / TB, TB>>>(poolp, GG * DD / 4);
    zero_kernel<<<1, GG / 4>>>(cntp, GG / 4);
    cnt_kernel<<<(NN + TB - 1) / TB, TB>>>(batch, cntp, NN);
    pool_kernel<<<(NN * 32 + TB - 1) / TB, TB>>>(xp, batch, poolp);
    mlp_kernel<<<1, 256>>>(poolp, cntp, pt, fc1w, fc1b, fc2w, fc2b, fclw, fclb, out);
}

// round 6
// speedup vs baseline: 2.1309x; 1.0252x over previous
#include <cuda_runtime.h>
#include <cuda_bf16.h>
#include <math.h>
#include <stdint.h>
#include <mma.h>

using namespace nvcuda;

#define NN 100000
#define NP 100096
#define EE 600000
#define DD 128
#define SS 3
#define GG 64
#define OUTD 2
#define NPS (SS * NP)

// ---------------- device scratch ----------------
__device__ float g_x[NP * DD];                 // x fp32 (GRU hold at i=0, pooling)
__device__ __nv_bfloat16 g_xb[NP * DD];        // x bf16 (GEMM A / gather input)
__device__ float g_h[NP * DD];                 // h fp32 (GRU hold at i=1)
__device__ __nv_bfloat16 g_hb[NP * DD];        // h bf16
__device__ __nv_bfloat16 g_aggb[NP * DD];      // gathered mean, bf16
__device__ float g_acc[NP * DD];               // edge-set accumulator fp32
__device__ __nv_bfloat16 g_gh[NP * 3 * DD];
__device__ __nv_bfloat16 g_gi[NP * 3 * DD];
__device__ float g_wc[SS * 2 * 3 * DD * DD];   // combined weights fp32 [384,128] x6
__device__ __nv_bfloat16 g_wihb[SS * 3 * DD * DD];
__device__ float g_pool[GG * DD];
__device__ float g_cnt[GG];
__device__ int   g_bsrc[EE];
__device__ int   g_ecnt[NPS];
__device__ int   g_ecur[NPS];
__device__ int   g_eoff[NPS + 1];

// ---------------- tiny utils ----------------
__global__ void zero_kernel(float* __restrict__ p, int n4) {
    int i = blockIdx.x * blockDim.x + threadIdx.x;
    if (i < n4) ((float4*)p)[i] = make_float4(0.f, 0.f, 0.f, 0.f);
}
// copy x->xp fp32 + xb bf16; zero pads of xp/xb/hb
__global__ void copy_pad_kernel(const float* __restrict__ x, float* __restrict__ xp,
                                __nv_bfloat16* __restrict__ xb,
                                __nv_bfloat16* __restrict__ hb) {
    int i = blockIdx.x * blockDim.x + threadIdx.x;   // NP*32 float4 slots
    if (i >= NP * 32) return;
    int n = i >> 5;
    float4 v = make_float4(0.f, 0.f, 0.f, 0.f);
    if (n < NN) {
        v = ((const float4*)x)[i];
    } else {
        ((float4*)xp)[(size_t)i] = v;
        *(__nv_bfloat162*)(hb + (size_t)i * 4)     = __floats2bfloat162_rn(0.f, 0.f);
        *(__nv_bfloat162*)(hb + (size_t)i * 4 + 2) = __floats2bfloat162_rn(0.f, 0.f);
    }
    if (n < NN) ((float4*)xp)[(size_t)i] = v;
    *(__nv_bfloat162*)(xb + (size_t)i * 4)     = __floats2bfloat162_rn(v.x, v.y);
    *(__nv_bfloat162*)(xb + (size_t)i * 4 + 2) = __floats2bfloat162_rn(v.z, v.w);
}
__global__ void cvt_bf16_kernel(const float* __restrict__ src,
                                __nv_bfloat16* __restrict__ dst, int n4) {
    int i = blockIdx.x * blockDim.x + threadIdx.x;
    if (i >= n4) return;
    float4 v = ((const float4*)src)[i];
    *(__nv_bfloat162*)(dst + (size_t)i * 4)     = __floats2bfloat162_rn(v.x, v.y);
    *(__nv_bfloat162*)(dst + (size_t)i * 4 + 2) = __floats2bfloat162_rn(v.z, v.w);
}
__global__ void zero2_ints(int* __restrict__ a, int* __restrict__ b, int n) {
    int i = blockIdx.x * blockDim.x + threadIdx.x;
    if (i < n) { a[i] = 0; b[i] = 0; }
}

// ---------------- CSR build ----------------
__global__ void ecount_kernel(const int* __restrict__ dst, const int* __restrict__ attr,
                              int* __restrict__ cnt, int E) {
    int e = blockIdx.x * blockDim.x + threadIdx.x;
    if (e < E) atomicAdd(&cnt[attr[e] * NP + dst[e]], 1);
}
__global__ void scan_kernel(const int* __restrict__ cnt, int* __restrict__ off, int n) {
    __shared__ int ssum[1024];
    int t = threadIdx.x;
    int per = (n + 1023) / 1024;
    int b0 = t * per;
    int b1 = b0 + per; if (b1 > n) b1 = n; if (b0 > n) b0 = n;
    int s = 0;
    for (int i = b0; i < b1; i++) s += cnt[i];
    ssum[t] = s;
    __syncthreads();
    for (int d = 1; d < 1024; d <<= 1) {
        int v = (t >= d) ? ssum[t - d] : 0;
        __syncthreads();
        ssum[t] += v;
        __syncthreads();
    }
    int run = (t == 0) ? 0 : ssum[t - 1];
    if (t == 1023) off[n] = ssum[1023];
    for (int i = b0; i < b1; i++) { off[i] = run; run += cnt[i]; }
}
__global__ void fill_kernel(const int* __restrict__ src, const int* __restrict__ dst,
                            const int* __restrict__ attr, const int* __restrict__ off,
                            int* __restrict__ cur, int* __restrict__ bsrc, int E) {
    int e = blockIdx.x * blockDim.x + threadIdx.x;
    if (e >= E) return;
    int idx = attr[e] * NP + dst[e];
    int pos = off[idx] + atomicAdd(&cur[idx], 1);
    bsrc[pos] = src[e];
}

// ---------------- gather (bf16 in/out): agg[n] = mean of feat[src] ----------
__global__ void gather_kernel(const int* __restrict__ off, const int* __restrict__ bsrc,
                              int s, const __nv_bfloat16* __restrict__ feat,
                              __nv_bfloat16* __restrict__ agg) {
    int w = (blockIdx.x * blockDim.x + threadIdx.x) >> 5;
    int lane = threadIdx.x & 31;
    if (w >= NP) return;
    int idx = s * NP + w;
    int e0 = off[idx], e1 = off[idx + 1];
    float a0 = 0.f, a1 = 0.f, a2 = 0.f, a3 = 0.f;
    for (int e = e0; e < e1; e++) {
        int sn = bsrc[e];
        uint2 u = *(const uint2*)(feat + (size_t)sn * DD + lane * 4);
        __nv_bfloat162 p0 = *(__nv_bfloat162*)&u.x;
        __nv_bfloat162 p1 = *(__nv_bfloat162*)&u.y;
        float2 f0 = __bfloat1622float2(p0), f1 = __bfloat1622float2(p1);
        a0 += f0.x; a1 += f0.y; a2 += f1.x; a3 += f1.y;
    }
    if (e1 > e0) {
        float inv = 1.0f / (float)(e1 - e0);
        a0 *= inv; a1 *= inv; a2 *= inv; a3 *= inv;
    }
    uint2 o;
    *(__nv_bfloat162*)&o.x = __floats2bfloat162_rn(a0, a1);
    *(__nv_bfloat162*)&o.y = __floats2bfloat162_rn(a2, a3);
    *(uint2*)(agg + (size_t)w * DD + lane * 4) = o;
}

// ================= bf16 WMMA GEMM: C = A[M,128] @ B[J,128]^T + bias ==========
// A bf16, B fp32 (converted at load). CTA tile 128x128, warp tile 64x64,
// 128 threads, K=128 resident. Dual mode / strided batch as before.
#define LDTB 136
#define LDC 132
#define BG_SMEM (256 * LDTB * 2)   // 69632 B

__global__ void __launch_bounds__(128, 2)
bf16_gemm(const __nv_bfloat16* __restrict__ A0, const float* __restrict__ B0,
          const float* __restrict__ bias0, void* __restrict__ C0v,
          const __nv_bfloat16* __restrict__ A1, const float* __restrict__ B1,
          const float* __restrict__ bias1, void* __restrict__ C1v,
          int J, int out_bf16, size_t sA, size_t sB, size_t sC) {
    const __nv_bfloat16* A;
    const float *B, *bias;
    void* C;
    if (A1 != nullptr) {
        if (blockIdx.z == 0) { A = A0; B = B0; bias = bias0; C = C0v; }
        else                 { A = A1; B = B1; bias = bias1; C = C1v; }
    } else {
        A = A0 + (size_t)blockIdx.z * sA;
        B = B0 + (size_t)blockIdx.z * sB;
        bias = bias0;
        C = (void*)((float*)C0v + (size_t)blockIdx.z * sC);
    }

    extern __shared__ char smx[];
    __nv_bfloat16* As = (__nv_bfloat16*)smx;
    __nv_bfloat16* Bs = As + 128 * LDTB;
    float* Cs = (float*)smx;

    int tid = threadIdx.x;
    int bm = blockIdx.y * 128;
    int bn = blockIdx.x * 128;

    // A tile: 128 rows x 128 bf16, copy via uint4 (8 bf16)
    for (int slot = tid; slot < 128 * 16; slot += 128) {
        int r = slot >> 4;
        int c8 = (slot & 15) * 8;
        uint4 u = *(const uint4*)(A + (size_t)(bm + r) * 128 + c8);
        *(uint4*)(As + r * LDTB + c8) = u;
    }
    // B tile: 128 rows x 128 fp32 -> bf16
    for (int slot = tid; slot < 128 * 32; slot += 128) {
        int r = slot >> 5;
        int c4 = (slot & 31) * 4;
        float4 w = *(const float4*)(B + (size_t)(bn + r) * 128 + c4);
        *(__nv_bfloat162*)(Bs + r * LDTB + c4)     = __floats2bfloat162_rn(w.x, w.y);
        *(__nv_bfloat162*)(Bs + r * LDTB + c4 + 2) = __floats2bfloat162_rn(w.z, w.w);
    }
    __syncthreads();

    int warp = tid >> 5;
    int row0 = (warp >> 1) * 64;   // 2x2 warp grid, 64x64 tiles
    int col0 = (warp & 1) * 64;

    wmma::fragment<wmma::accumulator, 16, 16, 16, float> acc[4][4];
#pragma unroll
    for (int i = 0; i < 4; i++)
#pragma unroll
        for (int j = 0; j < 4; j++) wmma::fill_fragment(acc[i][j], 0.0f);

#pragma unroll
    for (int k = 0; k < 8; k++) {
        wmma::fragment<wmma::matrix_a, 16, 16, 16, __nv_bfloat16, wmma::row_major> a[4];
        wmma::fragment<wmma::matrix_b, 16, 16, 16, __nv_bfloat16, wmma::col_major> b[4];
#pragma unroll
        for (int i = 0; i < 4; i++)
            wmma::load_matrix_sync(a[i], As + (row0 + i * 16) * LDTB + k * 16, LDTB);
#pragma unroll
        for (int j = 0; j < 4; j++)
            wmma::load_matrix_sync(b[j], Bs + (col0 + j * 16) * LDTB + k * 16, LDTB);
#pragma unroll
        for (int i = 0; i < 4; i++)
#pragma unroll
            for (int j = 0; j < 4; j++)
                wmma::mma_sync(acc[i][j], a[i], b[j], acc[i][j]);
    }
    __syncthreads();

#pragma unroll
    for (int i = 0; i < 4; i++)
#pragma unroll
        for (int j = 0; j < 4; j++)
            wmma::store_matrix_sync(Cs + (row0 + i * 16) * LDC + col0 + j * 16,
                                    acc[i][j], LDC, wmma::mem_row_major);
    __syncthreads();

    for (int slot = tid; slot < 128 * 32; slot += 128) {
        int r = slot >> 5;
        int c4 = (slot & 31) * 4;
        float4 v = *(float4*)(Cs + r * LDC + c4);
        if (bias != nullptr) {
            v.x += bias[bn + c4 + 0];
            v.y += bias[bn + c4 + 1];
            v.z += bias[bn + c4 + 2];
            v.w += bias[bn + c4 + 3];
        }
        if (out_bf16) {
            __nv_bfloat16* crow = (__nv_bfloat16*)C + (size_t)(bm + r) * J + bn + c4;
            *(__nv_bfloat162*)(crow)     = __floats2bfloat162_rn(v.x, v.y);
            *(__nv_bfloat162*)(crow + 2) = __floats2bfloat162_rn(v.z, v.w);
        } else {
            *(float4*)((float*)C + (size_t)(bm + r) * J + bn + c4) = v;
        }
    }
}

// ---------------- GRU elementwise combine ----------------
__device__ __forceinline__ float sigf(float x) { return 1.0f / (1.0f + expf(-x)); }

__device__ __forceinline__ float4 ldbf4(const __nv_bfloat16* p) {
    uint2 u = *(const uint2*)p;
    __nv_bfloat162 a = *(__nv_bfloat162*)&u.x;
    __nv_bfloat162 b = *(__nv_bfloat162*)&u.y;
    float2 fa = __bfloat1622float2(a), fb = __bfloat1622float2(b);
    return make_float4(fa.x, fa.y, fb.x, fb.y);
}
__device__ __forceinline__ void stbf4(__nv_bfloat16* p, float4 v) {
    uint2 u;
    *(__nv_bfloat162*)&u.x = __floats2bfloat162_rn(v.x, v.y);
    *(__nv_bfloat162*)&u.y = __floats2bfloat162_rn(v.z, v.w);
    *(uint2*)p = u;
}

// mode 0: hout=o, houtb=o           (i=0: h feeds next GRU + gather)
// mode 1: acc=o                     (i=1, s=0)
// mode 2: acc+=o                    (i=1, s=1)
// mode 3: x=(acc+o)/3 -> hout,houtb (i=1, s=2: produce next-pass x)
__global__ void gru_combine_kernel(const __nv_bfloat16* __restrict__ gi,
                                   const __nv_bfloat16* __restrict__ gh,
                                   const float* __restrict__ hold,
                                   float* __restrict__ hout,
                                   __nv_bfloat16* __restrict__ houtb,
                                   float* __restrict__ accb, int mode) {
    int idx = blockIdx.x * blockDim.x + threadIdx.x;
    if (idx >= NN * 32) return;
    int n = idx >> 5;
    int c = (idx & 31) * 4;
    const __nv_bfloat16* gir = gi + (size_t)n * 384;
    const __nv_bfloat16* ghr = gh + (size_t)n * 384;
    float4 ir = ldbf4(gir + c);
    float4 iz = ldbf4(gir + 128 + c);
    float4 in4 = ldbf4(gir + 256 + c);
    float4 hr = ldbf4(ghr + c);
    float4 hz = ldbf4(ghr + 128 + c);
    float4 hn = ldbf4(ghr + 256 + c);
    float4 h = *(const float4*)(hold + (size_t)n * 128 + c);
    float4 o;
    { float r = sigf(ir.x + hr.x), z = sigf(iz.x + hz.x);
      float nn = tanhf(in4.x + r * hn.x); o.x = (1.f - z) * nn + z * h.x; }
    { float r = sigf(ir.y + hr.y), z = sigf(iz.y + hz.y);
      float nn = tanhf(in4.y + r * hn.y); o.y = (1.f - z) * nn + z * h.y; }
    { float r = sigf(ir.z + hr.z), z = sigf(iz.z + hz.z);
      float nn = tanhf(in4.z + r * hn.z); o.z = (1.f - z) * nn + z * h.z; }
    { float r = sigf(ir.w + hr.w), z = sigf(iz.w + hz.w);
      float nn = tanhf(in4.w + r * hn.w); o.w = (1.f - z) * nn + z * h.w; }
    size_t p = (size_t)n * 128 + c;
    if (mode == 0) {
        *(float4*)(hout + p) = o;
        stbf4(houtb + p, o);
    } else if (mode == 1) {
        *(float4*)(accb + p) = o;
    } else if (mode == 2) {
        float4 av = *(float4*)(accb + p);
        av.x += o.x; av.y += o.y; av.z += o.z; av.w += o.w;
        *(float4*)(accb + p) = av;
    } else {
        float4 av = *(float4*)(accb + p);
        float4 xv;
        xv.x = (av.x + o.x) * (1.0f / 3.0f);
        xv.y = (av.y + o.y) * (1.0f / 3.0f);
        xv.z = (av.z + o.z) * (1.0f / 3.0f);
        xv.w = (av.w + o.w) * (1.0f / 3.0f);
        *(float4*)(hout + p) = xv;
        stbf4(houtb + p, xv);
    }
}

// ---------------- pooling / MLP ----------------
__global__ void cnt_kernel(const int* __restrict__ batch, float* __restrict__ cnt, int n) {
    int i = blockIdx.x * blockDim.x + threadIdx.x;
    if (i < n) atomicAdd(&cnt[batch[i]], 1.0f);
}
__global__ void pool_kernel(const float* __restrict__ x, const int* __restrict__ batch,
                            float* __restrict__ pool) {
    int idx = blockIdx.x * blockDim.x + threadIdx.x;
    if (idx >= NN * 32) return;
    int n = idx >> 5;
    int c = (idx & 31) * 4;
    int g = batch[n];
    float4 v = *(const float4*)(x + (size_t)n * 128 + c);
    float* o = pool + (size_t)g * 128 + c;
    asm volatile("red.global.add.v4.f32 [%0], {%1,%2,%3,%4};"
                 :: "l"(o), "f"(v.x), "f"(v.y), "f"(v.z), "f"(v.w) : "memory");
}
__global__ void mlp_kernel(const float* __restrict__ pool, const float* __restrict__ cnt,
                           const float* __restrict__ pt,
                           const float* __restrict__ fc1w, const float* __restrict__ fc1b,
                           const float* __restrict__ fc2w, const float* __restrict__ fc2b,
                           const float* __restrict__ fclw, const float* __restrict__ fclb,
                           float* __restrict__ out) {
    __shared__ float h1[GG * 80];
    __shared__ float h2[GG * 80];
    int tid = threadIdx.x;
    for (int t = tid; t < GG * 80; t += blockDim.x) {
        int g = t / 80, j = t - (t / 80) * 80;
        float ic = 1.0f / fmaxf(cnt[g], 1.0f);
        float acc = fc1b[j];
        const float* w = fc1w + j * 129;
        const float* p = pool + g * 128;
        for (int k = 0; k < 128; k++) acc = fmaf(p[k] * ic, w[k], acc);
        acc = fmaf(pt[g], w[128], acc);
        h1[t] = acc > 0.f ? acc : 0.01f * acc;
    }
    __syncthreads();
    for (int t = tid; t < GG * 80; t += blockDim.x) {
        int g = t / 80, j = t - (t / 80) * 80;
        float acc = fc2b[j];
        const float* w = fc2w + j * 80;
        const float* hh = h1 + g * 80;
        for (int k = 0; k < 80; k++) acc = fmaf(hh[k], w[k], acc);
        h2[t] = acc > 0.f ? acc : 0.01f * acc;
    }
    __syncthreads();
    for (int t = tid; t < GG * OUTD; t += blockDim.x) {
        int g = t / OUTD, o = t - (t / OUTD) * OUTD;
        float acc = fclb[o];
        const float* w = fclw + o * 80;
        const float* hh = h2 + g * 80;
        for (int k = 0; k < 80; k++) acc = fmaf(hh[k], w[k], acc);
        out[t] = acc;
    }
}

// ---------------- host launcher ----------------
extern "C" void kernel_launch(void* const* d_in, const int* in_sizes, int n_in,
                              void* d_out, int out_size) {
    (void)in_sizes; (void)n_in; (void)out_size;
    const float* x     = (const float*)d_in[0];
    const int*   eidx  = (const int*)d_in[1];
    const int*   eattr = (const int*)d_in[2];
    const int*   batch = (const int*)d_in[3];
    const float* pt    = (const float*)d_in[4];
    const float* W     = (const float*)d_in[5];
    const float* wih   = (const float*)d_in[6];
    const float* whh   = (const float*)d_in[7];
    const float* bih   = (const float*)d_in[8];
    const float* bhh   = (const float*)d_in[9];
    const float* fc1w  = (const float*)d_in[10];
    const float* fc1b  = (const float*)d_in[11];
    const float* fc2w  = (const float*)d_in[12];
    const float* fc2b  = (const float*)d_in[13];
    const float* fclw  = (const float*)d_in[14];
    const float* fclb  = (const float*)d_in[15];
    float* out = (float*)d_out;

    const int* src = eidx;
    const int* dst = eidx + EE;

    float *xp, *hp, *accp, *wcp, *poolp, *cntp;
    __nv_bfloat16 *xb, *hb, *aggb, *ghp, *gip, *wihb;
    int *bsrcp, *ecntp, *ecurp, *eoffp;
    cudaGetSymbolAddress((void**)&xp,    g_x);
    cudaGetSymbolAddress((void**)&xb,    g_xb);
    cudaGetSymbolAddress((void**)&hp,    g_h);
    cudaGetSymbolAddress((void**)&hb,    g_hb);
    cudaGetSymbolAddress((void**)&aggb,  g_aggb);
    cudaGetSymbolAddress((void**)&accp,  g_acc);
    cudaGetSymbolAddress((void**)&ghp,   g_gh);
    cudaGetSymbolAddress((void**)&gip,   g_gi);
    cudaGetSymbolAddress((void**)&wcp,   g_wc);
    cudaGetSymbolAddress((void**)&wihb,  g_wihb);
    cudaGetSymbolAddress((void**)&poolp, g_pool);
    cudaGetSymbolAddress((void**)&cntp,  g_cnt);
    cudaGetSymbolAddress((void**)&bsrcp, g_bsrc);
    cudaGetSymbolAddress((void**)&ecntp, g_ecnt);
    cudaGetSymbolAddress((void**)&ecurp, g_ecur);
    cudaGetSymbolAddress((void**)&eoffp, g_eoff);

    cudaFuncSetAttribute(bf16_gemm, cudaFuncAttributeMaxDynamicSharedMemorySize, BG_SMEM);

    const int TB = 256;
    const int GT = 128;                     // GEMM block threads
    dim3 main_grid1(3, NP / 128, 1);
    dim3 main_grid2(3, NP / 128, 2);
    dim3 wc_grid(1, 3, 2);

    // 0: copy + pad + bf16 mirror
    copy_pad_kernel<<<(NP * 32 + TB - 1) / TB, TB>>>(x, xp, xb, hb);
    // 1: wih -> bf16
    cvt_bf16_kernel<<<(SS * 384 * 128 / 4 + TB - 1) / TB, TB>>>(wih, wihb, SS * 384 * 32);
    // 2: zero CSR arrays
    zero2_ints<<<(NPS + TB - 1) / TB, TB>>>(ecntp, ecurp, NPS);
    // 3 (PROFILED): gh GEMM for step (0,0,0)
    bf16_gemm<<<main_grid1, GT, BG_SMEM>>>(xb, whh, bhh, ghp,
                                           nullptr, nullptr, nullptr, nullptr,
                                           384, 1, 0, 0, 0);
    // CSR build
    ecount_kernel<<<(EE + TB - 1) / TB, TB>>>(dst, eattr, ecntp, EE);
    scan_kernel<<<1, 1024>>>(ecntp, eoffp, NPS);
    fill_kernel<<<(EE + TB - 1) / TB, TB>>>(src, dst, eattr, eoffp, ecurp, bsrcp, EE);
    // combined weights Wc[s,i] = wih[s] @ W[s,i]  (fp32 out)
    for (int s = 0; s < SS; s++)
        bf16_gemm<<<wc_grid, GT, BG_SMEM>>>(
            wihb + (size_t)s * 384 * 128, W + (size_t)(s * 2) * 128 * 128, nullptr,
            wcp + (size_t)(s * 2) * 384 * 128,
            nullptr, nullptr, nullptr, nullptr,
            128, 0, (size_t)0, (size_t)(128 * 128), (size_t)(384 * 128));

    // --- main GGNN loop ---
    for (int pass = 0; pass < 2; pass++) {
        for (int s = 0; s < SS; s++) {
            for (int i = 0; i < 2; i++) {
                const __nv_bfloat16* ain = (i == 0) ? xb : hb;
                const float* hold = (i == 0) ? xp : hp;
                const float* wc_si = wcp + (size_t)(s * 2 + i) * 384 * 128;
                gather_kernel<<<(NP * 32 + TB - 1) / TB, TB>>>(eoffp, bsrcp, s, ain, aggb);
                if (pass == 0 && s == 0 && i == 0) {
                    bf16_gemm<<<main_grid1, GT, BG_SMEM>>>(aggb, wc_si, bih, gip,
                                                           nullptr, nullptr, nullptr, nullptr,
                                                           384, 1, 0, 0, 0);
                } else {
                    bf16_gemm<<<main_grid2, GT, BG_SMEM>>>(
                        ain, whh + (size_t)s * 384 * 128, bhh + s * 384, ghp,
                        aggb, wc_si, bih + s * 384, gip,
                        384, 1, 0, 0, 0);
                }
                int mode = (i == 0) ? 0 : ((s == 0) ? 1 : ((s == 1) ? 2 : 3));
                gru_combine_kernel<<<(NN * 32 + TB - 1) / TB, TB>>>(
                    gip, ghp, hold, (mode == 3) ? xp : hp, (mode == 3) ? xb : hb,
                    accp, mode);
            }
        }
    }

    // --- pooling + MLP ---
    zero_kernel<<<(GG * DD / 4 + TB - 1) / TB, TB>>>(poolp, GG * DD / 4);
    zero_kernel<<<1, GG / 4>>>(cntp, GG / 4);
    cnt_kernel<<<(NN + TB - 1) / TB, TB>>>(batch, cntp, NN);
    pool_kernel<<<(NN * 32 + TB - 1) / TB, TB>>>(xp, batch, poolp);
    mlp_kernel<<<1, 256>>>(poolp, cntp, pt, fc1w, fc1b, fc2w, fc2b, fclw, fclb, out);
}

// round 7
// speedup vs baseline: 2.9330x; 1.3764x over previous
#include <cuda_runtime.h>
#include <cuda_bf16.h>
#include <math.h>
#include <stdint.h>
#include <mma.h>

using namespace nvcuda;

#define NN 100000
#define NP 100096
#define EE 600000
#define DD 128
#define SS 3
#define GG 64
#define OUTD 2
#define NPS (SS * NP)
#define M_TILES (NP / 128)          // 782

// ---------------- device scratch ----------------
__device__ float g_x[NP * DD];
__device__ __nv_bfloat16 g_xb[NP * DD];
__device__ float g_h[NP * DD];
__device__ __nv_bfloat16 g_hb[NP * DD];
__device__ __nv_bfloat16 g_aggb[NP * DD];
__device__ float g_acc[NP * DD];
__device__ __nv_bfloat16 g_gh[NP * 3 * DD];
__device__ __nv_bfloat16 g_gi[NP * 3 * DD];
__device__ __nv_bfloat16 g_wcb[SS * 2 * 3 * DD * DD];   // combined weights bf16
__device__ __nv_bfloat16 g_wihb[SS * 3 * DD * DD];
__device__ __nv_bfloat16 g_whhb[SS * 3 * DD * DD];
__device__ __nv_bfloat16 g_Wb[SS * 2 * DD * DD];
__device__ float g_pool[GG * DD];
__device__ float g_cnt[GG];
__device__ int   g_bsrc[EE];
__device__ int   g_ecnt[NPS];
__device__ int   g_ecur[NPS];
__device__ int   g_eoff[NPS + 1];

// ---------------- tiny utils ----------------
__global__ void zero_kernel(float* __restrict__ p, int n4) {
    int i = blockIdx.x * blockDim.x + threadIdx.x;
    if (i < n4) ((float4*)p)[i] = make_float4(0.f, 0.f, 0.f, 0.f);
}
__global__ void copy_pad_kernel(const float* __restrict__ x, float* __restrict__ xp,
                                __nv_bfloat16* __restrict__ xb,
                                __nv_bfloat16* __restrict__ hb) {
    int i = blockIdx.x * blockDim.x + threadIdx.x;
    if (i >= NP * 32) return;
    int n = i >> 5;
    float4 v = make_float4(0.f, 0.f, 0.f, 0.f);
    if (n < NN) {
        v = ((const float4*)x)[i];
    } else {
        *(__nv_bfloat162*)(hb + (size_t)i * 4)     = __floats2bfloat162_rn(0.f, 0.f);
        *(__nv_bfloat162*)(hb + (size_t)i * 4 + 2) = __floats2bfloat162_rn(0.f, 0.f);
    }
    ((float4*)xp)[(size_t)i] = v;
    *(__nv_bfloat162*)(xb + (size_t)i * 4)     = __floats2bfloat162_rn(v.x, v.y);
    *(__nv_bfloat162*)(xb + (size_t)i * 4 + 2) = __floats2bfloat162_rn(v.z, v.w);
}
__global__ void cvt_bf16_kernel(const float* __restrict__ src,
                                __nv_bfloat16* __restrict__ dst, int n4) {
    int i = blockIdx.x * blockDim.x + threadIdx.x;
    if (i >= n4) return;
    float4 v = ((const float4*)src)[i];
    *(__nv_bfloat162*)(dst + (size_t)i * 4)     = __floats2bfloat162_rn(v.x, v.y);
    *(__nv_bfloat162*)(dst + (size_t)i * 4 + 2) = __floats2bfloat162_rn(v.z, v.w);
}
__global__ void zero2_ints(int* __restrict__ a, int* __restrict__ b, int n) {
    int i = blockIdx.x * blockDim.x + threadIdx.x;
    if (i < n) { a[i] = 0; b[i] = 0; }
}

// ---------------- CSR build ----------------
__global__ void ecount_kernel(const int* __restrict__ dst, const int* __restrict__ attr,
                              int* __restrict__ cnt, int E) {
    int e = blockIdx.x * blockDim.x + threadIdx.x;
    if (e < E) atomicAdd(&cnt[attr[e] * NP + dst[e]], 1);
}
__global__ void scan_kernel(const int* __restrict__ cnt, int* __restrict__ off, int n) {
    __shared__ int ssum[1024];
    int t = threadIdx.x;
    int per = (n + 1023) / 1024;
    int b0 = t * per;
    int b1 = b0 + per; if (b1 > n) b1 = n; if (b0 > n) b0 = n;
    int s = 0;
    for (int i = b0; i < b1; i++) s += cnt[i];
    ssum[t] = s;
    __syncthreads();
    for (int d = 1; d < 1024; d <<= 1) {
        int v = (t >= d) ? ssum[t - d] : 0;
        __syncthreads();
        ssum[t] += v;
        __syncthreads();
    }
    int run = (t == 0) ? 0 : ssum[t - 1];
    if (t == 1023) off[n] = ssum[1023];
    for (int i = b0; i < b1; i++) { off[i] = run; run += cnt[i]; }
}
__global__ void fill_kernel(const int* __restrict__ src, const int* __restrict__ dst,
                            const int* __restrict__ attr, const int* __restrict__ off,
                            int* __restrict__ cur, int* __restrict__ bsrc, int E) {
    int e = blockIdx.x * blockDim.x + threadIdx.x;
    if (e >= E) return;
    int idx = attr[e] * NP + dst[e];
    int pos = off[idx] + atomicAdd(&cur[idx], 1);
    bsrc[pos] = src[e];
}

// ---------------- gather (bf16): agg[n] = mean of feat[src] ----------
__global__ void gather_kernel(const int* __restrict__ off, const int* __restrict__ bsrc,
                              int s, const __nv_bfloat16* __restrict__ feat,
                              __nv_bfloat16* __restrict__ agg) {
    int w = (blockIdx.x * blockDim.x + threadIdx.x) >> 5;
    int lane = threadIdx.x & 31;
    if (w >= NP) return;
    int idx = s * NP + w;
    int e0 = off[idx], e1 = off[idx + 1];
    float a0 = 0.f, a1 = 0.f, a2 = 0.f, a3 = 0.f;
    for (int e = e0; e < e1; e++) {
        int sn = bsrc[e];
        uint2 u = *(const uint2*)(feat + (size_t)sn * DD + lane * 4);
        __nv_bfloat162 p0 = *(__nv_bfloat162*)&u.x;
        __nv_bfloat162 p1 = *(__nv_bfloat162*)&u.y;
        float2 f0 = __bfloat1622float2(p0), f1 = __bfloat1622float2(p1);
        a0 += f0.x; a1 += f0.y; a2 += f1.x; a3 += f1.y;
    }
    if (e1 > e0) {
        float inv = 1.0f / (float)(e1 - e0);
        a0 *= inv; a1 *= inv; a2 *= inv; a3 *= inv;
    }
    uint2 o;
    *(__nv_bfloat162*)&o.x = __floats2bfloat162_rn(a0, a1);
    *(__nv_bfloat162*)&o.y = __floats2bfloat162_rn(a2, a3);
    *(uint2*)(agg + (size_t)w * DD + lane * 4) = o;
}

// ================= streaming bf16 WMMA GEMM ==================================
// C[M,J] = A[M,128] @ B[J,128]^T + bias. A,B bf16 in gmem. CTA owns one 128-col
// N-tile (B resident) and strides over M-tiles with cp.async double buffering.
#define LDTB 136
#define LDC2 132
#define SMB 34816                       // one 128x136 bf16 tile
#define BG_SMEM (3 * SMB)               // B + A0 + A1 = 104448

__device__ __forceinline__ void cp16(void* s, const void* g) {
    uint32_t sa = (uint32_t)__cvta_generic_to_shared(s);
    asm volatile("cp.async.cg.shared.global [%0], [%1], 16;" :: "r"(sa), "l"(g));
}
__device__ __forceinline__ void tile_load_async(__nv_bfloat16* dstS,
                                                const __nv_bfloat16* srcG, int tid) {
    for (int slot = tid; slot < 2048; slot += 256) {
        int r = slot >> 4;
        int c8 = (slot & 15) * 8;
        cp16(dstS + r * LDTB + c8, srcG + (size_t)r * 128 + c8);
    }
}

__global__ void __launch_bounds__(256, 2)
bf16_gemm(const __nv_bfloat16* __restrict__ A0, const __nv_bfloat16* __restrict__ B0,
          const float* __restrict__ bias0, void* __restrict__ C0v,
          const __nv_bfloat16* __restrict__ A1, const __nv_bfloat16* __restrict__ B1,
          const float* __restrict__ bias1, void* __restrict__ C1v,
          int J, int out_bf16, int mtiles, size_t sA, size_t sB, size_t sC) {
    const __nv_bfloat16 *A, *B;
    const float* bias;
    void* C;
    if (A1 != nullptr) {
        if (blockIdx.z == 0) { A = A0; B = B0; bias = bias0; C = C0v; }
        else                 { A = A1; B = B1; bias = bias1; C = C1v; }
    } else {
        A = A0 + (size_t)blockIdx.z * sA;
        B = B0 + (size_t)blockIdx.z * sB;
        bias = bias0;
        C = (void*)((__nv_bfloat16*)C0v + (size_t)blockIdx.z * sC * (out_bf16 ? 1 : 2));
    }

    extern __shared__ char smx[];
    __nv_bfloat16* Bs = (__nv_bfloat16*)smx;
    __nv_bfloat16* Abuf0 = (__nv_bfloat16*)(smx + SMB);
    __nv_bfloat16* Abuf1 = (__nv_bfloat16*)(smx + 2 * SMB);

    int tid = threadIdx.x;
    int warp = tid >> 5;
    int row0 = (warp >> 1) * 32;
    int col0 = (warp & 1) * 64;
    int bn = blockIdx.x * 128;

    int mt = blockIdx.y;
    if (mt >= mtiles) return;

    // initial: B tile + first A tile (group 0)
    tile_load_async(Bs, B + (size_t)bn * 128, tid);
    tile_load_async(Abuf0, A + (size_t)mt * 128 * 128, tid);
    asm volatile("cp.async.commit_group;");

    int buf = 0;
    while (mt < mtiles) {
        int nxt = mt + gridDim.y;
        bool pf = (nxt < mtiles);
        __nv_bfloat16* Acur = buf ? Abuf1 : Abuf0;
        __nv_bfloat16* Aalt = buf ? Abuf0 : Abuf1;
        if (pf) {
            tile_load_async(Aalt, A + (size_t)nxt * 128 * 128, tid);
            asm volatile("cp.async.commit_group;");
            asm volatile("cp.async.wait_group 1;");
        } else {
            asm volatile("cp.async.wait_group 0;");
        }
        __syncthreads();

        wmma::fragment<wmma::accumulator, 16, 16, 16, float> acc[2][4];
#pragma unroll
        for (int i = 0; i < 2; i++)
#pragma unroll
            for (int j = 0; j < 4; j++) wmma::fill_fragment(acc[i][j], 0.0f);

#pragma unroll
        for (int k = 0; k < 8; k++) {
            wmma::fragment<wmma::matrix_a, 16, 16, 16, __nv_bfloat16, wmma::row_major> a[2];
            wmma::fragment<wmma::matrix_b, 16, 16, 16, __nv_bfloat16, wmma::col_major> b[4];
#pragma unroll
            for (int i = 0; i < 2; i++)
                wmma::load_matrix_sync(a[i], Acur + (row0 + i * 16) * LDTB + k * 16, LDTB);
#pragma unroll
            for (int j = 0; j < 4; j++)
                wmma::load_matrix_sync(b[j], Bs + (col0 + j * 16) * LDTB + k * 16, LDTB);
#pragma unroll
            for (int i = 0; i < 2; i++)
#pragma unroll
                for (int j = 0; j < 4; j++)
                    wmma::mma_sync(acc[i][j], a[i], b[j], acc[i][j]);
        }
        __syncthreads();

        // epilogue: two 64-row halves staged in the just-consumed A buffer
        float* Cs = (float*)Acur;
        int bm = mt * 128;
#pragma unroll
        for (int h = 0; h < 2; h++) {
            if ((warp >> 2) == h) {
                int lr = row0 - h * 64;
#pragma unroll
                for (int i = 0; i < 2; i++)
#pragma unroll
                    for (int j = 0; j < 4; j++)
                        wmma::store_matrix_sync(Cs + (lr + i * 16) * LDC2 + col0 + j * 16,
                                                acc[i][j], LDC2, wmma::mem_row_major);
            }
            __syncthreads();
            for (int slot = tid; slot < 64 * 32; slot += 256) {
                int r = slot >> 5;
                int c4 = (slot & 31) * 4;
                float4 v = *(float4*)(Cs + r * LDC2 + c4);
                if (bias != nullptr) {
                    v.x += bias[bn + c4 + 0];
                    v.y += bias[bn + c4 + 1];
                    v.z += bias[bn + c4 + 2];
                    v.w += bias[bn + c4 + 3];
                }
                int grow = bm + h * 64 + r;
                if (out_bf16) {
                    __nv_bfloat16* crow = (__nv_bfloat16*)C + (size_t)grow * J + bn + c4;
                    *(__nv_bfloat162*)(crow)     = __floats2bfloat162_rn(v.x, v.y);
                    *(__nv_bfloat162*)(crow + 2) = __floats2bfloat162_rn(v.z, v.w);
                } else {
                    *(float4*)((float*)C + (size_t)grow * J + bn + c4) = v;
                }
            }
            __syncthreads();
        }
        mt = nxt;
        buf ^= 1;
    }
}

// ---------------- GRU elementwise combine ----------------
__device__ __forceinline__ float sigf(float x) { return 1.0f / (1.0f + expf(-x)); }

__device__ __forceinline__ float4 ldbf4(const __nv_bfloat16* p) {
    uint2 u = *(const uint2*)p;
    __nv_bfloat162 a = *(__nv_bfloat162*)&u.x;
    __nv_bfloat162 b = *(__nv_bfloat162*)&u.y;
    float2 fa = __bfloat1622float2(a), fb = __bfloat1622float2(b);
    return make_float4(fa.x, fa.y, fb.x, fb.y);
}
__device__ __forceinline__ void stbf4(__nv_bfloat16* p, float4 v) {
    uint2 u;
    *(__nv_bfloat162*)&u.x = __floats2bfloat162_rn(v.x, v.y);
    *(__nv_bfloat162*)&u.y = __floats2bfloat162_rn(v.z, v.w);
    *(uint2*)p = u;
}

__global__ void gru_combine_kernel(const __nv_bfloat16* __restrict__ gi,
                                   const __nv_bfloat16* __restrict__ gh,
                                   const float* __restrict__ hold,
                                   float* __restrict__ hout,
                                   __nv_bfloat16* __restrict__ houtb,
                                   float* __restrict__ accb, int mode) {
    int idx = blockIdx.x * blockDim.x + threadIdx.x;
    if (idx >= NN * 32) return;
    int n = idx >> 5;
    int c = (idx & 31) * 4;
    const __nv_bfloat16* gir = gi + (size_t)n * 384;
    const __nv_bfloat16* ghr = gh + (size_t)n * 384;
    float4 ir = ldbf4(gir + c);
    float4 iz = ldbf4(gir + 128 + c);
    float4 in4 = ldbf4(gir + 256 + c);
    float4 hr = ldbf4(ghr + c);
    float4 hz = ldbf4(ghr + 128 + c);
    float4 hn = ldbf4(ghr + 256 + c);
    float4 h = *(const float4*)(hold + (size_t)n * 128 + c);
    float4 o;
    { float r = sigf(ir.x + hr.x), z = sigf(iz.x + hz.x);
      float nn = tanhf(in4.x + r * hn.x); o.x = (1.f - z) * nn + z * h.x; }
    { float r = sigf(ir.y + hr.y), z = sigf(iz.y + hz.y);
      float nn = tanhf(in4.y + r * hn.y); o.y = (1.f - z) * nn + z * h.y; }
    { float r = sigf(ir.z + hr.z), z = sigf(iz.z + hz.z);
      float nn = tanhf(in4.z + r * hn.z); o.z = (1.f - z) * nn + z * h.z; }
    { float r = sigf(ir.w + hr.w), z = sigf(iz.w + hz.w);
      float nn = tanhf(in4.w + r * hn.w); o.w = (1.f - z) * nn + z * h.w; }
    size_t p = (size_t)n * 128 + c;
    if (mode == 0) {
        *(float4*)(hout + p) = o;
        stbf4(houtb + p, o);
    } else if (mode == 1) {
        *(float4*)(accb + p) = o;
    } else if (mode == 2) {
        float4 av = *(float4*)(accb + p);
        av.x += o.x; av.y += o.y; av.z += o.z; av.w += o.w;
        *(float4*)(accb + p) = av;
    } else {
        float4 av = *(float4*)(accb + p);
        float4 xv;
        xv.x = (av.x + o.x) * (1.0f / 3.0f);
        xv.y = (av.y + o.y) * (1.0f / 3.0f);
        xv.z = (av.z + o.z) * (1.0f / 3.0f);
        xv.w = (av.w + o.w) * (1.0f / 3.0f);
        *(float4*)(hout + p) = xv;
        stbf4(houtb + p, xv);
    }
}

// ---------------- pooling / MLP ----------------
__global__ void cnt_kernel(const int* __restrict__ batch, float* __restrict__ cnt, int n) {
    int i = blockIdx.x * blockDim.x + threadIdx.x;
    if (i < n) atomicAdd(&cnt[batch[i]], 1.0f);
}
__global__ void pool_kernel(const float* __restrict__ x, const int* __restrict__ batch,
                            float* __restrict__ pool) {
    int idx = blockIdx.x * blockDim.x + threadIdx.x;
    if (idx >= NN * 32) return;
    int n = idx >> 5;
    int c = (idx & 31) * 4;
    int g = batch[n];
    float4 v = *(const float4*)(x + (size_t)n * 128 + c);
    float* o = pool + (size_t)g * 128 + c;
    asm volatile("red.global.add.v4.f32 [%0], {%1,%2,%3,%4};"
                 :: "l"(o), "f"(v.x), "f"(v.y), "f"(v.z), "f"(v.w) : "memory");
}
__global__ void mlp_kernel(const float* __restrict__ pool, const float* __restrict__ cnt,
                           const float* __restrict__ pt,
                           const float* __restrict__ fc1w, const float* __restrict__ fc1b,
                           const float* __restrict__ fc2w, const float* __restrict__ fc2b,
                           const float* __restrict__ fclw, const float* __restrict__ fclb,
                           float* __restrict__ out) {
    __shared__ float h1[GG * 80];
    __shared__ float h2[GG * 80];
    int tid = threadIdx.x;
    for (int t = tid; t < GG * 80; t += blockDim.x) {
        int g = t / 80, j = t - (t / 80) * 80;
        float ic = 1.0f / fmaxf(cnt[g], 1.0f);
        float acc = fc1b[j];
        const float* w = fc1w + j * 129;
        const float* p = pool + g * 128;
        for (int k = 0; k < 128; k++) acc = fmaf(p[k] * ic, w[k], acc);
        acc = fmaf(pt[g], w[128], acc);
        h1[t] = acc > 0.f ? acc : 0.01f * acc;
    }
    __syncthreads();
    for (int t = tid; t < GG * 80; t += blockDim.x) {
        int g = t / 80, j = t - (t / 80) * 80;
        float acc = fc2b[j];
        const float* w = fc2w + j * 80;
        const float* hh = h1 + g * 80;
        for (int k = 0; k < 80; k++) acc = fmaf(hh[k], w[k], acc);
        h2[t] = acc > 0.f ? acc : 0.01f * acc;
    }
    __syncthreads();
    for (int t = tid; t < GG * OUTD; t += blockDim.x) {
        int g = t / OUTD, o = t - (t / OUTD) * OUTD;
        float acc = fclb[o];
        const float* w = fclw + o * 80;
        const float* hh = h2 + g * 80;
        for (int k = 0; k < 80; k++) acc = fmaf(hh[k], w[k], acc);
        out[t] = acc;
    }
}

// ---------------- host launcher ----------------
extern "C" void kernel_launch(void* const* d_in, const int* in_sizes, int n_in,
                              void* d_out, int out_size) {
    (void)in_sizes; (void)n_in; (void)out_size;
    const float* x     = (const float*)d_in[0];
    const int*   eidx  = (const int*)d_in[1];
    const int*   eattr = (const int*)d_in[2];
    const int*   batch = (const int*)d_in[3];
    const float* pt    = (const float*)d_in[4];
    const float* W     = (const float*)d_in[5];
    const float* wih   = (const float*)d_in[6];
    const float* whh   = (const float*)d_in[7];
    const float* bih   = (const float*)d_in[8];
    const float* bhh   = (const float*)d_in[9];
    const float* fc1w  = (const float*)d_in[10];
    const float* fc1b  = (const float*)d_in[11];
    const float* fc2w  = (const float*)d_in[12];
    const float* fc2b  = (const float*)d_in[13];
    const float* fclw  = (const float*)d_in[14];
    const float* fclb  = (const float*)d_in[15];
    float* out = (float*)d_out;

    const int* src = eidx;
    const int* dst = eidx + EE;

    float *xp, *hp, *accp, *poolp, *cntp;
    __nv_bfloat16 *xb, *hb, *aggb, *ghp, *gip, *wcb, *wihb, *whhb, *Wb;
    int *bsrcp, *ecntp, *ecurp, *eoffp;
    cudaGetSymbolAddress((void**)&xp,    g_x);
    cudaGetSymbolAddress((void**)&xb,    g_xb);
    cudaGetSymbolAddress((void**)&hp,    g_h);
    cudaGetSymbolAddress((void**)&hb,    g_hb);
    cudaGetSymbolAddress((void**)&aggb,  g_aggb);
    cudaGetSymbolAddress((void**)&accp,  g_acc);
    cudaGetSymbolAddress((void**)&ghp,   g_gh);
    cudaGetSymbolAddress((void**)&gip,   g_gi);
    cudaGetSymbolAddress((void**)&wcb,   g_wcb);
    cudaGetSymbolAddress((void**)&wihb,  g_wihb);
    cudaGetSymbolAddress((void**)&whhb,  g_whhb);
    cudaGetSymbolAddress((void**)&Wb,    g_Wb);
    cudaGetSymbolAddress((void**)&poolp, g_pool);
    cudaGetSymbolAddress((void**)&cntp,  g_cnt);
    cudaGetSymbolAddress((void**)&bsrcp, g_bsrc);
    cudaGetSymbolAddress((void**)&ecntp, g_ecnt);
    cudaGetSymbolAddress((void**)&ecurp, g_ecur);
    cudaGetSymbolAddress((void**)&eoffp, g_eoff);

    cudaFuncSetAttribute(bf16_gemm, cudaFuncAttributeMaxDynamicSharedMemorySize, BG_SMEM);

    const int TB = 256;
    dim3 main_grid1(3, 99, 1);
    dim3 main_grid2(3, 99, 2);
    dim3 wc_grid(1, 3, 2);

    // 0: copy + pad + bf16 mirror
    copy_pad_kernel<<<(NP * 32 + TB - 1) / TB, TB>>>(x, xp, xb, hb);
    // 1: whh -> bf16 (needed by launch 3)
    cvt_bf16_kernel<<<(SS * 384 * 32 + TB - 1) / TB, TB>>>(whh, whhb, SS * 384 * 32);
    // 2: zero CSR arrays
    zero2_ints<<<(NPS + TB - 1) / TB, TB>>>(ecntp, ecurp, NPS);
    // 3 (PROFILED): gh GEMM for step (0,0,0)
    bf16_gemm<<<main_grid1, TB, BG_SMEM>>>(xb, whhb, bhh, ghp,
                                           nullptr, nullptr, nullptr, nullptr,
                                           384, 1, M_TILES, 0, 0, 0);
    // remaining weight conversions + CSR build
    cvt_bf16_kernel<<<(SS * 384 * 32 + TB - 1) / TB, TB>>>(wih, wihb, SS * 384 * 32);
    cvt_bf16_kernel<<<(SS * 2 * 128 * 32 + TB - 1) / TB, TB>>>(W, Wb, SS * 2 * 128 * 32);
    ecount_kernel<<<(EE + TB - 1) / TB, TB>>>(dst, eattr, ecntp, EE);
    scan_kernel<<<1, 1024>>>(ecntp, eoffp, NPS);
    fill_kernel<<<(EE + TB - 1) / TB, TB>>>(src, dst, eattr, eoffp, ecurp, bsrcp, EE);
    // combined weights Wc[s,i] = wih[s] @ W[s,i]  (bf16 out, batched over i via z)
    for (int s = 0; s < SS; s++)
        bf16_gemm<<<wc_grid, TB, BG_SMEM>>>(
            wihb + (size_t)s * 384 * 128, Wb + (size_t)(s * 2) * 128 * 128, nullptr,
            wcb + (size_t)(s * 2) * 384 * 128,
            nullptr, nullptr, nullptr, nullptr,
            128, 1, 3, (size_t)0, (size_t)(128 * 128), (size_t)(384 * 128));

    // --- main GGNN loop ---
    for (int pass = 0; pass < 2; pass++) {
        for (int s = 0; s < SS; s++) {
            for (int i = 0; i < 2; i++) {
                const __nv_bfloat16* ain = (i == 0) ? xb : hb;
                const float* hold = (i == 0) ? xp : hp;
                const __nv_bfloat16* wc_si = wcb + (size_t)(s * 2 + i) * 384 * 128;
                gather_kernel<<<(NP * 32 + TB - 1) / TB, TB>>>(eoffp, bsrcp, s, ain, aggb);
                if (pass == 0 && s == 0 && i == 0) {
                    bf16_gemm<<<main_grid1, TB, BG_SMEM>>>(
                        aggb, wc_si, bih, gip,
                        nullptr, nullptr, nullptr, nullptr,
                        384, 1, M_TILES, 0, 0, 0);
                } else {
                    bf16_gemm<<<main_grid2, TB, BG_SMEM>>>(
                        ain, whhb + (size_t)s * 384 * 128, bhh + s * 384, ghp,
                        aggb, wc_si, bih + s * 384, gip,
                        384, 1, M_TILES, 0, 0, 0);
                }
                int mode = (i == 0) ? 0 : ((s == 0) ? 1 : ((s == 1) ? 2 : 3));
                gru_combine_kernel<<<(NN * 32 + TB - 1) / TB, TB>>>(
                    gip, ghp, hold, (mode == 3) ? xp : hp, (mode == 3) ? xb : hb,
                    accp, mode);
            }
        }
    }

    // --- pooling + MLP ---
    zero_kernel<<<(GG * DD / 4 + TB - 1) / TB, TB>>>(poolp, GG * DD / 4);
    zero_kernel<<<1, GG / 4>>>(cntp, GG / 4);
    cnt_kernel<<<(NN + TB - 1) / TB, TB>>>(batch, cntp, NN);
    pool_kernel<<<(NN * 32 + TB - 1) / TB, TB>>>(xp, batch, poolp);
    mlp_kernel<<<1, 256>>>(poolp, cntp, pt, fc1w, fc1b, fc2w, fc2b, fclw, fclb, out);
}